// round 15
// baseline (speedup 1.0000x reference)
#include <cuda_runtime.h>
#include <math.h>

// ---------------------------------------------------------------------------
// HyperNetworkDecoder: K=2, P=4096, 8 layers of width 64.
// hyper_kernel: generate per-(k,layer) weights once, stored directly as
// tf32 B-fragments for mma.sync.m16n8k8 (32 output-splits, 512 blocks).
// decode_kernel: tensor-core decoder, 4-way n-split, weights read straight
// from global (L1-resident; one k per SM) — no smem weight stage. 256
// blocks x 256 threads (32 pts, 2 A-tiles x 4 n-splits), 3 blocks/SM.
// ---------------------------------------------------------------------------

#define KB 2
typedef unsigned int u32;

__device__ __align__(16) u32 g_W0u[KB * 8192];          // l0 W  B-frag tf32
__device__ __align__(16) u32 g_Wlu[KB * 7 * 4096];      // l1..7 W B-frag tf32
__device__ __align__(16) float g_b [KB * 8 * 64];       // biases [k][l][n]

__device__ __forceinline__ u32 tf32c(float f)
{ u32 u; asm("cvt.rna.tf32.f32 %0, %1;" : "=r"(u) : "f"(f)); return u; }

// ---------------------------------------------------------------------------
// Kernel 1: hypernetwork. grid = (k,l) x 32 output-splits = 512 blocks,
// 512 threads: 2 j-groups of 256 handle half the 64-deep reduction each.
// ---------------------------------------------------------------------------
__global__ void __launch_bounds__(512) hyper_kernel(
    const float* __restrict__ latent_tokens,
    const float* __restrict__ token_embeddings,
    const float* __restrict__ h_W0,  const float* __restrict__ h_b0,
    const float* __restrict__ h_ln_s0, const float* __restrict__ h_ln_b0,
    const float* __restrict__ w_W0,  const float* __restrict__ w_b0,
    const float* __restrict__ bb_W0, const float* __restrict__ bb_b0,
    const float* __restrict__ h_W,   const float* __restrict__ h_b,
    const float* __restrict__ h_ln_s, const float* __restrict__ h_ln_b,
    const float* __restrict__ w_W,   const float* __restrict__ w_b,
    const float* __restrict__ bb_W,  const float* __restrict__ bb_b)
{
    __shared__ float chunk[128];
    __shared__ float part[4][64];
    __shared__ float pre[64];
    __shared__ float hbuf[64];
    __shared__ float wpart[512];

    const int tid = threadIdx.x;
    const int bx  = blockIdx.x;
    const int sp  = bx & 31;
    const int kl  = bx >> 5;
    const int k   = kl >> 3;
    const int l   = kl & 7;

    if (tid < 128)
        chunk[tid] = (tid < 64) ? latent_tokens[(k * 8 + l) * 64 + tid]
                                : token_embeddings[l * 64 + (tid - 64)];
    __syncthreads();

    const float* hWp = (l == 0) ? h_W0 : (h_W + (l - 1) * 128 * 64);
    if (tid < 256) {
        const int q = tid >> 6, j = tid & 63;
        float acc = 0.f;
        #pragma unroll
        for (int i = 0; i < 32; i++) {
            int ii = q * 32 + i;
            acc = fmaf(chunk[ii], __ldg(hWp + ii * 64 + j), acc);
        }
        part[q][j] = acc;
    }
    __syncthreads();
    if (tid < 64) {
        float hb = (l == 0) ? __ldg(h_b0 + tid) : __ldg(h_b + (l - 1) * 64 + tid);
        pre[tid] = part[0][tid] + part[1][tid] + part[2][tid] + part[3][tid] + hb;
    }
    __syncthreads();
    if (tid < 64) {
        float s1 = 0.f, s2 = 0.f;
        #pragma unroll 8
        for (int i = 0; i < 64; i++) { float v = pre[i]; s1 += v; s2 += v * v; }
        float mu   = s1 * (1.f / 64.f);
        float var  = s2 * (1.f / 64.f) - mu * mu;
        float rstd = rsqrtf(var + 1e-6f);
        float ls = (l == 0) ? __ldg(h_ln_s0 + tid) : __ldg(h_ln_s + (l - 1) * 64 + tid);
        float lb = (l == 0) ? __ldg(h_ln_b0 + tid) : __ldg(h_ln_b + (l - 1) * 64 + tid);
        float h  = fmaf((pre[tid] - mu) * rstd, ls, lb);
        hbuf[tid] = fmaxf(h, 0.f);
    }
    __syncthreads();

    const int OUT  = (l == 0) ? 8064 : 4096;
    const int CH   = OUT >> 5;                  // 252 or 128
    const int o0   = sp * CH, oend = o0 + CH;
    const float* wWp = (l == 0) ? w_W0 : (w_W + (l - 1) * 64 * 4096);
    const float* wbp = (l == 0) ? w_b0 : (w_b + (l - 1) * 4096);

    const int g  = tid >> 8;
    const int tt = tid & 255;
    const int o  = o0 + tt;
    const bool ok = (tt < CH);

    float acc = (ok && g == 0) ? __ldg(wbp + o) : 0.f;
    const int j0 = g * 32;
    #pragma unroll 8
    for (int jj = 0; jj < 32; jj++) {
        if (ok) acc = fmaf(hbuf[j0 + jj], __ldg(wWp + (j0 + jj) * OUT + o), acc);
    }
    wpart[tid & 511] = acc;
    __syncthreads();

    if (g == 0 && ok) {
        float v = acc + wpart[256 + tt];
        int n, m;
        if (l == 0) { n = o / 126; m = o - n * 126; }
        else        { n = o >> 6;  m = o & 63; }
        int kt = m >> 3, kk = m & 7;
        int nt = n >> 3, nn = n & 7;
        int lane = nn * 4 + (kk & 3);
        int slot = kk >> 2;
        int idx  = (kt * 8 + nt) * 64 + lane * 2 + slot;
        if (l == 0) g_W0u[k * 8192 + idx] = tf32c(v);
        else        g_Wlu[k * 28672 + (l - 1) * 4096 + idx] = tf32c(v);
    }

    if (sp == 0) {
        if (l == 0 && tid < 128) {        // zero-pad m = 126,127 for all n
            int n = tid & 63, m = 126 + (tid >> 6);
            int kt = m >> 3, kk = m & 7;
            int nt = n >> 3, nn = n & 7;
            int idx = (kt * 8 + nt) * 64 + (nn * 4 + (kk & 3)) * 2 + (kk >> 2);
            g_W0u[k * 8192 + idx] = 0u;
        }
        if (tid < 64) {
            const float* bWp = (l == 0) ? bb_W0 : (bb_W + (l - 1) * 64 * 64);
            float accb = (l == 0) ? __ldg(bb_b0 + tid) : __ldg(bb_b + (l - 1) * 64 + tid);
            #pragma unroll 8
            for (int j = 0; j < 64; j++)
                accb = fmaf(hbuf[j], __ldg(bWp + j * 64 + tid), accb);
            g_b[(k * 8 + l) * 64 + tid] = accb;
        }
    }
}

// ---------------------------------------------------------------------------
// Float-only accurate sin: 2-term Cody-Waite reduction by pi, then sinf.
// ---------------------------------------------------------------------------
__device__ __forceinline__ float acc_sin(float x)
{
    float q = rintf(x * 0.318309886183790672f);
    float r = fmaf(-q, 3.14159274101257324f, x);
    r = fmaf(-q, -8.74227800037e-8f, r);
    float s = sinf(r);
    return (((int)q) & 1) ? -s : s;
}

#define MMA_TF32(C, AV, BV) \
    asm volatile("mma.sync.aligned.m16n8k8.row.col.f32.tf32.tf32.f32 " \
        "{%0,%1,%2,%3}, {%4,%5,%6,%7}, {%8,%9}, {%0,%1,%2,%3};" \
        : "+f"((C)[0]), "+f"((C)[1]), "+f"((C)[2]), "+f"((C)[3]) \
        : "r"((AV).x), "r"((AV).y), "r"((AV).z), "r"((AV).w), \
          "r"((BV).x), "r"((BV).y))

#define TILE_BAR(T) asm volatile("bar.sync %0, 128;" :: "r"((T) + 1) : "memory")

// ---------------------------------------------------------------------------
// Kernel 2: tensor-core decoder. 256 blocks x 256 threads, 32 pts/block
// (one k per block: k = bx >> 7). 8 warps: t = wid&1 (A-tile of 16 pts),
// ns = wid>>1 (n-tiles {2ns, 2ns+1}). Weights read from GLOBAL (L1-hot,
// one k per SM); only A tiles + LN/bias/reduction live in (static) smem.
// ---------------------------------------------------------------------------
__global__ void __launch_bounds__(256, 3) decode_kernel(
    const float* __restrict__ rays,
    const float* __restrict__ ln_s0, const float* __restrict__ ln_b0,
    const float* __restrict__ ln_s,  const float* __restrict__ ln_b,
    const float* __restrict__ rgb_W, const float* __restrict__ rgb_b,
    float* __restrict__ out)
{
    __shared__ __align__(16) u32   sA[4096];      // 2 tiles x 2048
    __shared__ float  sBias[512];
    __shared__ float  sLN[1024];
    __shared__ float4 sRed[128];                  // 32 pts x 4 ns
    __shared__ float4 sRGB[128];

    const int tid  = threadIdx.x;
    const int wid  = tid >> 5;
    const int lane = tid & 31;
    const int t    = wid & 1;       // A-tile 0/1
    const int ns   = wid >> 1;      // n-split 0..3
    const int gid  = lane >> 2;     // row group 0..7
    const int tig  = lane & 3;      // thread in group
    const int bx   = blockIdx.x;
    const int k    = bx >> 7;

    const u32* W0g = g_W0u + k * 8192;
    const u32* Wlg = g_Wlu + k * 28672;

    // ---- stage biases + LN params ----
    sBias[tid]       = __ldg(g_b + k * 512 + tid);
    sBias[tid + 256] = __ldg(g_b + k * 512 + 256 + tid);
    #pragma unroll
    for (int i = tid; i < 1024; i += 256) {
        int l = i >> 7, j = i & 127;
        float v;
        if (l == 0) v = (j < 64) ? __ldg(ln_s0 + j) : __ldg(ln_b0 + j - 64);
        else        v = (j < 64) ? __ldg(ln_s + (l - 1) * 64 + j)
                                 : __ldg(ln_b + (l - 1) * 64 + j - 64);
        sLN[i] = v;
    }

    // ---- positional encoding into A-fragment layout (8 lanes/point) ----
    {
        const int pb = tid >> 3;            // point in block 0..31
        const int s  = tid & 7;
        const int pl = pb & 15;
        u32* Ar = sA + (pb >> 4) * 2048;
        const float* r = rays + (bx * 32 + pb) * 6;
        float ox = __ldg(r + 0), oy = __ldg(r + 1), oz = __ldg(r + 2);
        float dx = __ldg(r + 3), dy = __ldg(r + 4), dz = __ldg(r + 5);
        float pv[6];
        pv[0] = dx; pv[1] = dy; pv[2] = dz;
        pv[3] = oy * dz - oz * dy;
        pv[4] = oz * dx - ox * dz;
        pv[5] = ox * dy - oy * dx;
        auto sta = [&](int m, float v) {
            int kt = m >> 3, c = m & 7;
            int ln = (pl & 7) * 4 + (c & 3);
            int sl = (pl >> 3) + 2 * (c >> 2);
            Ar[kt * 128 + ln * 4 + sl] = tf32c(v);
        };
        if (s == 6) {
            #pragma unroll
            for (int cm = 0; cm < 6; cm++) sta(cm, pv[cm]);
        }
        if (s == 7) { sta(126, 0.f); sta(127, 0.f); }
        const float PIH = 1.57079632679489662f;
        for (int f = s; f < 10; f += 8) {
            float fr = (float)(1 << f);
            #pragma unroll
            for (int cm = 0; cm < 6; cm++) {
                float a = pv[cm] * fr;
                sta(6 + f * 6 + cm, acc_sin(a));
                sta(66 + f * 6 + cm, acc_sin(a + PIH));
            }
        }
    }
    __syncthreads();          // the ONLY block-wide barrier

    u32* At = sA + t * 2048;
    const int nt0 = 2 * ns;               // this warp's n-tiles
    const int pb0 = t * 16 + gid;         // this thread's points: pb0, pb0+8

    float C[2][4];
    float y[2][4];

    #pragma unroll 1
    for (int l = 0; l < 8; l++) {
        const u32* Wl = (l == 0) ? W0g : (Wlg + (l - 1) * 4096);
        const int KT = (l == 0) ? 16 : 8;

        #pragma unroll
        for (int q = 0; q < 2; q++) {
            int n0 = (nt0 + q) * 8 + 2 * tig;
            float b0v = sBias[l * 64 + n0];
            float b1v = sBias[l * 64 + n0 + 1];
            C[q][0] = b0v; C[q][1] = b1v;
            C[q][2] = b0v; C[q][3] = b1v;
        }

        #pragma unroll 8
        for (int kt = 0; kt < KT; kt++) {
            uint4 av = *(const uint4*)(At + kt * 128 + lane * 4);
            uint2 bv0 = __ldg((const uint2*)(Wl + (kt * 8 + nt0)     * 64 + lane * 2));
            uint2 bv1 = __ldg((const uint2*)(Wl + (kt * 8 + nt0 + 1) * 64 + lane * 2));
            MMA_TF32(C[0], av, bv0);
            MMA_TF32(C[1], av, bv1);
        }

        // ---- LN partials: shuffle in 4-lane group, combine via smem ----
        float s1a = 0.f, s2a = 0.f, s1b = 0.f, s2b = 0.f;
        #pragma unroll
        for (int q = 0; q < 2; q++) {
            s1a += C[q][0] + C[q][1];
            s2a  = fmaf(C[q][0], C[q][0], fmaf(C[q][1], C[q][1], s2a));
            s1b += C[q][2] + C[q][3];
            s2b  = fmaf(C[q][2], C[q][2], fmaf(C[q][3], C[q][3], s2b));
        }
        #pragma unroll
        for (int mm = 1; mm < 4; mm <<= 1) {
            s1a += __shfl_xor_sync(0xffffffffu, s1a, mm, 32);
            s2a += __shfl_xor_sync(0xffffffffu, s2a, mm, 32);
            s1b += __shfl_xor_sync(0xffffffffu, s1b, mm, 32);
            s2b += __shfl_xor_sync(0xffffffffu, s2b, mm, 32);
        }
        if (tig == 0)
            sRed[pb0 * 4 + ns] = make_float4(s1a, s2a, s1b, s2b);
        TILE_BAR(t);

        float S1a = 0.f, S2a = 0.f, S1b = 0.f, S2b = 0.f;
        #pragma unroll
        for (int j = 0; j < 4; j++) {
            float4 v = sRed[pb0 * 4 + j];
            S1a += v.x; S2a += v.y; S1b += v.z; S2b += v.w;
        }
        float mu0 = S1a * (1.f / 64.f);
        float mu1 = S1b * (1.f / 64.f);
        float rs0 = rsqrtf(S2a * (1.f / 64.f) - mu0 * mu0 + 1e-6f);
        float rs1 = rsqrtf(S2b * (1.f / 64.f) - mu1 * mu1 + 1e-6f);

        #pragma unroll
        for (int q = 0; q < 2; q++) {
            int n0 = (nt0 + q) * 8 + 2 * tig;
            float ls0 = sLN[l * 128 + n0],      ls1 = sLN[l * 128 + n0 + 1];
            float lb0 = sLN[l * 128 + 64 + n0], lb1 = sLN[l * 128 + 64 + n0 + 1];
            y[q][0] = fmaxf(fmaf((C[q][0] - mu0) * rs0, ls0, lb0), 0.f);
            y[q][1] = fmaxf(fmaf((C[q][1] - mu0) * rs0, ls1, lb1), 0.f);
            y[q][2] = fmaxf(fmaf((C[q][2] - mu1) * rs1, ls0, lb0), 0.f);
            y[q][3] = fmaxf(fmaf((C[q][3] - mu1) * rs1, ls1, lb1), 0.f);
            if (l < 7) {
                int nt = nt0 + q;
                int c0 = n0 & 7;
                int b0i = nt * 128 + (gid * 4 + (c0 & 3)) * 4 + 2 * (c0 >> 2);
                At[b0i]     = tf32c(y[q][0]);     // row gid
                At[b0i + 1] = tf32c(y[q][2]);     // row gid+8
                int c1 = c0 + 1;
                int b1i = nt * 128 + (gid * 4 + (c1 & 3)) * 4 + 2 * (c1 >> 2);
                At[b1i]     = tf32c(y[q][1]);
                At[b1i + 1] = tf32c(y[q][3]);
            }
        }
        if (l < 7) TILE_BAR(t);
    }

    // ---- rgb head + sigmoid ----
    {
        float r0[3] = {0.f, 0.f, 0.f};
        float r1[3] = {0.f, 0.f, 0.f};
        #pragma unroll
        for (int q = 0; q < 2; q++) {
            int n0 = (nt0 + q) * 8 + 2 * tig;
            #pragma unroll
            for (int ch = 0; ch < 3; ch++) {
                float w0 = __ldg(rgb_W + n0 * 3 + ch);
                float w1 = __ldg(rgb_W + (n0 + 1) * 3 + ch);
                r0[ch] = fmaf(y[q][0], w0, fmaf(y[q][1], w1, r0[ch]));
                r1[ch] = fmaf(y[q][2], w0, fmaf(y[q][3], w1, r1[ch]));
            }
        }
        #pragma unroll
        for (int mm = 1; mm < 4; mm <<= 1) {
            #pragma unroll
            for (int ch = 0; ch < 3; ch++) {
                r0[ch] += __shfl_xor_sync(0xffffffffu, r0[ch], mm, 32);
                r1[ch] += __shfl_xor_sync(0xffffffffu, r1[ch], mm, 32);
            }
        }
        if (tig == 0) {
            sRGB[pb0 * 4 + ns]       = make_float4(r0[0], r0[1], r0[2], 0.f);
            sRGB[(pb0 + 8) * 4 + ns] = make_float4(r1[0], r1[1], r1[2], 0.f);
        }
        TILE_BAR(t);
        if (ns == 0 && lane < 16) {
            int p = t * 16 + lane;
            float4 a0 = sRGB[p * 4 + 0];
            float4 a1 = sRGB[p * 4 + 1];
            float4 a2 = sRGB[p * 4 + 2];
            float4 a3 = sRGB[p * 4 + 3];
            float v0 = a0.x + a1.x + a2.x + a3.x + __ldg(rgb_b + 0);
            float v1 = a0.y + a1.y + a2.y + a3.y + __ldg(rgb_b + 1);
            float v2 = a0.z + a1.z + a2.z + a3.z + __ldg(rgb_b + 2);
            int gp = bx * 32 + p;
            out[gp * 3 + 0] = 1.f / (1.f + expf(-v0));
            out[gp * 3 + 1] = 1.f / (1.f + expf(-v1));
            out[gp * 3 + 2] = 1.f / (1.f + expf(-v2));
        }
    }
}

// ---------------------------------------------------------------------------
extern "C" void kernel_launch(void* const* d_in, const int* in_sizes, int n_in,
                              void* d_out, int out_size)
{
    const float* rays    = (const float*)d_in[0];
    const float* lat     = (const float*)d_in[1];
    const float* temb    = (const float*)d_in[2];
    const float* h_W0    = (const float*)d_in[3];
    const float* h_b0    = (const float*)d_in[4];
    const float* h_ln_s0 = (const float*)d_in[5];
    const float* h_ln_b0 = (const float*)d_in[6];
    const float* w_W0    = (const float*)d_in[7];
    const float* w_b0    = (const float*)d_in[8];
    const float* bb_W0   = (const float*)d_in[9];
    const float* bb_b0   = (const float*)d_in[10];
    const float* ln_s0   = (const float*)d_in[11];
    const float* ln_b0   = (const float*)d_in[12];
    const float* h_W     = (const float*)d_in[13];
    const float* h_b     = (const float*)d_in[14];
    const float* h_ln_s  = (const float*)d_in[15];
    const float* h_ln_b  = (const float*)d_in[16];
    const float* w_W     = (const float*)d_in[17];
    const float* w_b     = (const float*)d_in[18];
    const float* bb_W    = (const float*)d_in[19];
    const float* bb_b    = (const float*)d_in[20];
    const float* ln_s    = (const float*)d_in[21];
    const float* ln_b    = (const float*)d_in[22];
    const float* rgb_W   = (const float*)d_in[23];
    const float* rgb_b   = (const float*)d_in[24];
    float* out = (float*)d_out;

    hyper_kernel<<<512, 512>>>(lat, temb, h_W0, h_b0, h_ln_s0, h_ln_b0,
                               w_W0, w_b0, bb_W0, bb_b0,
                               h_W, h_b, h_ln_s, h_ln_b,
                               w_W, w_b, bb_W, bb_b);
    decode_kernel<<<256, 256>>>(rays, ln_s0, ln_b0, ln_s, ln_b,
                                rgb_W, rgb_b, out);
}

// round 16
// speedup vs baseline: 1.0882x; 1.0882x over previous
#include <cuda_runtime.h>
#include <math.h>

// ---------------------------------------------------------------------------
// HyperNetworkDecoder: K=2, P=4096, 8 layers of width 64.
// h_kernel  (grid 16):  h = relu(LN(chunk@hW+hb)) once per (k,l); also bias b.
// w_kernel  (grid 512): stream W = h @ wW + wb into tf32 B-fragments.
// decode    (grid 512 x 128): tensor-core decoder; block = one 16-point
// A-tile x 4 n-split warps; weights read from global (L1-hot); plain
// __syncthreads() for the LN exchange. 3.5 blocks/SM balanced.
// ---------------------------------------------------------------------------

#define KB 2
typedef unsigned int u32;

__device__ __align__(16) u32 g_W0u[KB * 8192];          // l0 W  B-frag tf32
__device__ __align__(16) u32 g_Wlu[KB * 7 * 4096];      // l1..7 W B-frag tf32
__device__ __align__(16) float g_b [KB * 8 * 64];       // biases [k][l][n]
__device__ __align__(16) float g_h [KB * 8 * 64];       // hidden h [k][l][64]

__device__ __forceinline__ u32 tf32c(float f)
{ u32 u; asm("cvt.rna.tf32.f32 %0, %1;" : "=r"(u) : "f"(f)); return u; }

// ---------------------------------------------------------------------------
// Kernel 1a: h + bias. grid = 16 blocks (one per (k,l)), 256 threads.
// ---------------------------------------------------------------------------
__global__ void __launch_bounds__(256) h_kernel(
    const float* __restrict__ latent_tokens,
    const float* __restrict__ token_embeddings,
    const float* __restrict__ h_W0,  const float* __restrict__ h_b0,
    const float* __restrict__ h_ln_s0, const float* __restrict__ h_ln_b0,
    const float* __restrict__ bb_W0, const float* __restrict__ bb_b0,
    const float* __restrict__ h_W,   const float* __restrict__ h_b,
    const float* __restrict__ h_ln_s, const float* __restrict__ h_ln_b,
    const float* __restrict__ bb_W,  const float* __restrict__ bb_b)
{
    __shared__ float chunk[128];
    __shared__ float part[4][64];
    __shared__ float pre[64];
    __shared__ float hbuf[64];

    const int tid = threadIdx.x;
    const int k   = blockIdx.x >> 3;
    const int l   = blockIdx.x & 7;

    if (tid < 128)
        chunk[tid] = (tid < 64) ? __ldg(latent_tokens + (k * 8 + l) * 64 + tid)
                                : __ldg(token_embeddings + l * 64 + (tid - 64));
    __syncthreads();

    const float* hWp = (l == 0) ? h_W0 : (h_W + (l - 1) * 128 * 64);
    {
        const int q = tid >> 6, j = tid & 63;
        float acc = 0.f;
        #pragma unroll
        for (int i = 0; i < 32; i++) {
            int ii = q * 32 + i;
            acc = fmaf(chunk[ii], __ldg(hWp + ii * 64 + j), acc);
        }
        part[q][j] = acc;
    }
    __syncthreads();
    if (tid < 64) {
        float hb = (l == 0) ? __ldg(h_b0 + tid) : __ldg(h_b + (l - 1) * 64 + tid);
        pre[tid] = part[0][tid] + part[1][tid] + part[2][tid] + part[3][tid] + hb;
    }
    __syncthreads();
    if (tid < 64) {
        float s1 = 0.f, s2 = 0.f;
        #pragma unroll 8
        for (int i = 0; i < 64; i++) { float v = pre[i]; s1 += v; s2 += v * v; }
        float mu   = s1 * (1.f / 64.f);
        float var  = s2 * (1.f / 64.f) - mu * mu;
        float rstd = rsqrtf(var + 1e-6f);
        float ls = (l == 0) ? __ldg(h_ln_s0 + tid) : __ldg(h_ln_s + (l - 1) * 64 + tid);
        float lb = (l == 0) ? __ldg(h_ln_b0 + tid) : __ldg(h_ln_b + (l - 1) * 64 + tid);
        float h  = fmaxf(fmaf((pre[tid] - mu) * rstd, ls, lb), 0.f);
        hbuf[tid] = h;
        g_h[(k * 8 + l) * 64 + tid] = h;
    }
    __syncthreads();
    if (tid < 64) {
        const float* bWp = (l == 0) ? bb_W0 : (bb_W + (l - 1) * 64 * 64);
        float accb = (l == 0) ? __ldg(bb_b0 + tid) : __ldg(bb_b + (l - 1) * 64 + tid);
        #pragma unroll 8
        for (int j = 0; j < 64; j++)
            accb = fmaf(hbuf[j], __ldg(bWp + j * 64 + tid), accb);
        g_b[(k * 8 + l) * 64 + tid] = accb;
    }
}

// ---------------------------------------------------------------------------
// Kernel 1b: W streaming. grid = 16 x 32 splits = 512 blocks, 256 threads.
// Each thread computes one output o (64-deep j loop, coalesced LDG).
// ---------------------------------------------------------------------------
__global__ void __launch_bounds__(256) w_kernel(
    const float* __restrict__ w_W0, const float* __restrict__ w_b0,
    const float* __restrict__ w_W,  const float* __restrict__ w_b)
{
    __shared__ float hbuf[64];

    const int tid = threadIdx.x;
    const int bx  = blockIdx.x;
    const int sp  = bx & 31;
    const int kl  = bx >> 5;
    const int k   = kl >> 3;
    const int l   = kl & 7;

    if (tid < 64) hbuf[tid] = g_h[kl * 64 + tid];
    __syncthreads();

    const int OUT = (l == 0) ? 8064 : 4096;
    const int CH  = (OUT + 31) >> 5;               // 252 or 128
    const int o   = sp * CH + tid;
    const float* wWp = (l == 0) ? w_W0 : (w_W + (l - 1) * 64 * 4096);
    const float* wbp = (l == 0) ? w_b0 : (w_b + (l - 1) * 4096);

    if (tid < CH && o < OUT) {
        float acc = __ldg(wbp + o);
        #pragma unroll 8
        for (int j = 0; j < 64; j++)
            acc = fmaf(hbuf[j], __ldg(wWp + j * OUT + o), acc);
        int n, m;
        if (l == 0) { n = o / 126; m = o - n * 126; }
        else        { n = o >> 6;  m = o & 63; }
        int kt = m >> 3, kk = m & 7;
        int nt = n >> 3, nn = n & 7;
        int lane = nn * 4 + (kk & 3);
        int slot = kk >> 2;
        int idx  = (kt * 8 + nt) * 64 + lane * 2 + slot;
        if (l == 0) g_W0u[k * 8192 + idx] = tf32c(acc);
        else        g_Wlu[k * 28672 + (l - 1) * 4096 + idx] = tf32c(acc);
    }

    // zero-pad W0 rows m = 126,127 (once per k)
    if (l == 0 && sp == 0 && tid < 128) {
        int n = tid & 63, m = 126 + (tid >> 6);
        int kt = m >> 3, kk = m & 7;
        int nt = n >> 3, nn = n & 7;
        int idx = (kt * 8 + nt) * 64 + (nn * 4 + (kk & 3)) * 2 + (kk >> 2);
        g_W0u[k * 8192 + idx] = 0u;
    }
}

// ---------------------------------------------------------------------------
// Float-only accurate sin: 2-term Cody-Waite reduction by pi, then sinf.
// ---------------------------------------------------------------------------
__device__ __forceinline__ float acc_sin(float x)
{
    float q = rintf(x * 0.318309886183790672f);
    float r = fmaf(-q, 3.14159274101257324f, x);
    r = fmaf(-q, -8.74227800037e-8f, r);
    float s = sinf(r);
    return (((int)q) & 1) ? -s : s;
}

#define MMA_TF32(C, AV, BV) \
    asm volatile("mma.sync.aligned.m16n8k8.row.col.f32.tf32.tf32.f32 " \
        "{%0,%1,%2,%3}, {%4,%5,%6,%7}, {%8,%9}, {%0,%1,%2,%3};" \
        : "+f"((C)[0]), "+f"((C)[1]), "+f"((C)[2]), "+f"((C)[3]) \
        : "r"((AV).x), "r"((AV).y), "r"((AV).z), "r"((AV).w), \
          "r"((BV).x), "r"((BV).y))

// ---------------------------------------------------------------------------
// Kernel 2: tensor-core decoder. 512 blocks x 128 threads, 16 pts/block
// (k = bx >> 8). 4 warps = 4 n-splits of the single 16-point A-tile.
// Weights from GLOBAL (L1-hot). LN via smem partial exchange + syncthreads.
// ---------------------------------------------------------------------------
__global__ void __launch_bounds__(128, 6) decode_kernel(
    const float* __restrict__ rays,
    const float* __restrict__ ln_s0, const float* __restrict__ ln_b0,
    const float* __restrict__ ln_s,  const float* __restrict__ ln_b,
    const float* __restrict__ rgb_W, const float* __restrict__ rgb_b,
    float* __restrict__ out)
{
    __shared__ __align__(16) u32 sA[2048];
    __shared__ float  sBias[512];
    __shared__ float  sLN[1024];
    __shared__ float4 sRed[64];                   // 16 pts x 4 ns
    __shared__ float4 sRGB[64];

    const int tid  = threadIdx.x;
    const int ns   = tid >> 5;      // n-split 0..3
    const int lane = tid & 31;
    const int gid  = lane >> 2;     // row group 0..7
    const int tig  = lane & 3;      // thread in group
    const int bx   = blockIdx.x;
    const int k    = bx >> 8;

    const u32* W0g = g_W0u + k * 8192;
    const u32* Wlg = g_Wlu + k * 28672;

    // ---- stage biases + LN params ----
    #pragma unroll
    for (int i = tid; i < 512; i += 128) sBias[i] = __ldg(g_b + k * 512 + i);
    #pragma unroll
    for (int i = tid; i < 1024; i += 128) {
        int l = i >> 7, j = i & 127;
        float v;
        if (l == 0) v = (j < 64) ? __ldg(ln_s0 + j) : __ldg(ln_b0 + j - 64);
        else        v = (j < 64) ? __ldg(ln_s + (l - 1) * 64 + j)
                                 : __ldg(ln_b + (l - 1) * 64 + j - 64);
        sLN[i] = v;
    }

    // ---- positional encoding into A-fragment layout (8 lanes/point) ----
    {
        const int pb = tid >> 3;            // point in block 0..15
        const int s  = tid & 7;
        const float* r = rays + (bx * 16 + pb) * 6;
        float ox = __ldg(r + 0), oy = __ldg(r + 1), oz = __ldg(r + 2);
        float dx = __ldg(r + 3), dy = __ldg(r + 4), dz = __ldg(r + 5);
        float pv[6];
        pv[0] = dx; pv[1] = dy; pv[2] = dz;
        pv[3] = oy * dz - oz * dy;
        pv[4] = oz * dx - ox * dz;
        pv[5] = ox * dy - oy * dx;
        auto sta = [&](int m, float v) {
            int kt = m >> 3, c = m & 7;
            int ln = (pb & 7) * 4 + (c & 3);
            int sl = (pb >> 3) + 2 * (c >> 2);
            sA[kt * 128 + ln * 4 + sl] = tf32c(v);
        };
        if (s == 6) {
            #pragma unroll
            for (int cm = 0; cm < 6; cm++) sta(cm, pv[cm]);
        }
        if (s == 7) { sta(126, 0.f); sta(127, 0.f); }
        const float PIH = 1.57079632679489662f;
        for (int f = s; f < 10; f += 8) {
            float fr = (float)(1 << f);
            #pragma unroll
            for (int cm = 0; cm < 6; cm++) {
                float a = pv[cm] * fr;
                sta(6 + f * 6 + cm, acc_sin(a));
                sta(66 + f * 6 + cm, acc_sin(a + PIH));
            }
        }
    }
    __syncthreads();

    const int nt0 = 2 * ns;               // this warp's n-tiles
    const int pb0 = gid;                  // this thread's points: pb0, pb0+8

    float C[2][4];
    float y[2][4];

    #pragma unroll 1
    for (int l = 0; l < 8; l++) {
        const u32* Wl = (l == 0) ? W0g : (Wlg + (l - 1) * 4096);
        const int KT = (l == 0) ? 16 : 8;

        #pragma unroll
        for (int q = 0; q < 2; q++) {
            int n0 = (nt0 + q) * 8 + 2 * tig;
            float b0v = sBias[l * 64 + n0];
            float b1v = sBias[l * 64 + n0 + 1];
            C[q][0] = b0v; C[q][1] = b1v;
            C[q][2] = b0v; C[q][3] = b1v;
        }

        #pragma unroll 8
        for (int kt = 0; kt < KT; kt++) {
            uint4 av = *(const uint4*)(sA + kt * 128 + lane * 4);
            uint2 bv0 = __ldg((const uint2*)(Wl + (kt * 8 + nt0)     * 64 + lane * 2));
            uint2 bv1 = __ldg((const uint2*)(Wl + (kt * 8 + nt0 + 1) * 64 + lane * 2));
            MMA_TF32(C[0], av, bv0);
            MMA_TF32(C[1], av, bv1);
        }

        // ---- LN partials: shuffle in 4-lane group, combine via smem ----
        float s1a = 0.f, s2a = 0.f, s1b = 0.f, s2b = 0.f;
        #pragma unroll
        for (int q = 0; q < 2; q++) {
            s1a += C[q][0] + C[q][1];
            s2a  = fmaf(C[q][0], C[q][0], fmaf(C[q][1], C[q][1], s2a));
            s1b += C[q][2] + C[q][3];
            s2b  = fmaf(C[q][2], C[q][2], fmaf(C[q][3], C[q][3], s2b));
        }
        #pragma unroll
        for (int mm = 1; mm < 4; mm <<= 1) {
            s1a += __shfl_xor_sync(0xffffffffu, s1a, mm, 32);
            s2a += __shfl_xor_sync(0xffffffffu, s2a, mm, 32);
            s1b += __shfl_xor_sync(0xffffffffu, s1b, mm, 32);
            s2b += __shfl_xor_sync(0xffffffffu, s2b, mm, 32);
        }
        if (tig == 0)
            sRed[pb0 * 4 + ns] = make_float4(s1a, s2a, s1b, s2b);
        __syncthreads();

        float S1a = 0.f, S2a = 0.f, S1b = 0.f, S2b = 0.f;
        #pragma unroll
        for (int j = 0; j < 4; j++) {
            float4 v = sRed[pb0 * 4 + j];
            S1a += v.x; S2a += v.y; S1b += v.z; S2b += v.w;
        }
        float mu0 = S1a * (1.f / 64.f);
        float mu1 = S1b * (1.f / 64.f);
        float rs0 = rsqrtf(S2a * (1.f / 64.f) - mu0 * mu0 + 1e-6f);
        float rs1 = rsqrtf(S2b * (1.f / 64.f) - mu1 * mu1 + 1e-6f);

        #pragma unroll
        for (int q = 0; q < 2; q++) {
            int n0 = (nt0 + q) * 8 + 2 * tig;
            float ls0 = sLN[l * 128 + n0],      ls1 = sLN[l * 128 + n0 + 1];
            float lb0 = sLN[l * 128 + 64 + n0], lb1 = sLN[l * 128 + 64 + n0 + 1];
            y[q][0] = fmaxf(fmaf((C[q][0] - mu0) * rs0, ls0, lb0), 0.f);
            y[q][1] = fmaxf(fmaf((C[q][1] - mu0) * rs0, ls1, lb1), 0.f);
            y[q][2] = fmaxf(fmaf((C[q][2] - mu1) * rs1, ls0, lb0), 0.f);
            y[q][3] = fmaxf(fmaf((C[q][3] - mu1) * rs1, ls1, lb1), 0.f);
            if (l < 7) {
                int nt = nt0 + q;
                int c0 = n0 & 7;
                int b0i = nt * 128 + (gid * 4 + (c0 & 3)) * 4 + 2 * (c0 >> 2);
                sA[b0i]     = tf32c(y[q][0]);     // row gid
                sA[b0i + 1] = tf32c(y[q][2]);     // row gid+8
                int c1 = c0 + 1;
                int b1i = nt * 128 + (gid * 4 + (c1 & 3)) * 4 + 2 * (c1 >> 2);
                sA[b1i]     = tf32c(y[q][1]);
                sA[b1i + 1] = tf32c(y[q][3]);
            }
        }
        if (l < 7) __syncthreads();
    }

    // ---- rgb head + sigmoid ----
    {
        float r0[3] = {0.f, 0.f, 0.f};
        float r1[3] = {0.f, 0.f, 0.f};
        #pragma unroll
        for (int q = 0; q < 2; q++) {
            int n0 = (nt0 + q) * 8 + 2 * tig;
            #pragma unroll
            for (int ch = 0; ch < 3; ch++) {
                float w0 = __ldg(rgb_W + n0 * 3 + ch);
                float w1 = __ldg(rgb_W + (n0 + 1) * 3 + ch);
                r0[ch] = fmaf(y[q][0], w0, fmaf(y[q][1], w1, r0[ch]));
                r1[ch] = fmaf(y[q][2], w0, fmaf(y[q][3], w1, r1[ch]));
            }
        }
        #pragma unroll
        for (int mm = 1; mm < 4; mm <<= 1) {
            #pragma unroll
            for (int ch = 0; ch < 3; ch++) {
                r0[ch] += __shfl_xor_sync(0xffffffffu, r0[ch], mm, 32);
                r1[ch] += __shfl_xor_sync(0xffffffffu, r1[ch], mm, 32);
            }
        }
        if (tig == 0) {
            sRGB[pb0 * 4 + ns]       = make_float4(r0[0], r0[1], r0[2], 0.f);
            sRGB[(pb0 + 8) * 4 + ns] = make_float4(r1[0], r1[1], r1[2], 0.f);
        }
        __syncthreads();
        if (tid < 16) {
            float4 a0 = sRGB[tid * 4 + 0];
            float4 a1 = sRGB[tid * 4 + 1];
            float4 a2 = sRGB[tid * 4 + 2];
            float4 a3 = sRGB[tid * 4 + 3];
            float v0 = a0.x + a1.x + a2.x + a3.x + __ldg(rgb_b + 0);
            float v1 = a0.y + a1.y + a2.y + a3.y + __ldg(rgb_b + 1);
            float v2 = a0.z + a1.z + a2.z + a3.z + __ldg(rgb_b + 2);
            int gp = bx * 16 + tid;
            out[gp * 3 + 0] = 1.f / (1.f + expf(-v0));
            out[gp * 3 + 1] = 1.f / (1.f + expf(-v1));
            out[gp * 3 + 2] = 1.f / (1.f + expf(-v2));
        }
    }
}

// ---------------------------------------------------------------------------
extern "C" void kernel_launch(void* const* d_in, const int* in_sizes, int n_in,
                              void* d_out, int out_size)
{
    const float* rays    = (const float*)d_in[0];
    const float* lat     = (const float*)d_in[1];
    const float* temb    = (const float*)d_in[2];
    const float* h_W0    = (const float*)d_in[3];
    const float* h_b0    = (const float*)d_in[4];
    const float* h_ln_s0 = (const float*)d_in[5];
    const float* h_ln_b0 = (const float*)d_in[6];
    const float* w_W0    = (const float*)d_in[7];
    const float* w_b0    = (const float*)d_in[8];
    const float* bb_W0   = (const float*)d_in[9];
    const float* bb_b0   = (const float*)d_in[10];
    const float* ln_s0   = (const float*)d_in[11];
    const float* ln_b0   = (const float*)d_in[12];
    const float* h_W     = (const float*)d_in[13];
    const float* h_b     = (const float*)d_in[14];
    const float* h_ln_s  = (const float*)d_in[15];
    const float* h_ln_b  = (const float*)d_in[16];
    const float* w_W     = (const float*)d_in[17];
    const float* w_b     = (const float*)d_in[18];
    const float* bb_W    = (const float*)d_in[19];
    const float* bb_b    = (const float*)d_in[20];
    const float* ln_s    = (const float*)d_in[21];
    const float* ln_b    = (const float*)d_in[22];
    const float* rgb_W   = (const float*)d_in[23];
    const float* rgb_b   = (const float*)d_in[24];
    float* out = (float*)d_out;

    h_kernel<<<16, 256>>>(lat, temb, h_W0, h_b0, h_ln_s0, h_ln_b0,
                          bb_W0, bb_b0, h_W, h_b, h_ln_s, h_ln_b,
                          bb_W, bb_b);
    w_kernel<<<512, 256>>>(w_W0, w_b0, w_W, w_b);
    decode_kernel<<<512, 128>>>(rays, ln_s0, ln_b0, ln_s, ln_b,
                                rgb_W, rgb_b, out);
}

// round 17
// speedup vs baseline: 1.1798x; 1.0842x over previous
#include <cuda_runtime.h>
#include <math.h>

// ---------------------------------------------------------------------------
// HyperNetworkDecoder: K=2, P=4096, 8 layers of width 64.
// h_kernel  (grid 16):  h = relu(LN(chunk@hW+hb)) + bias b, fully parallel
//   (4-way split matvecs, all weight loads in flight).
// w_kernel  (grid 512): stream W = h @ wW + wb into tf32 B-fragments.
// decode    (grid 512 x 128): tensor-core decoder; block = one 16-point
// A-tile x 4 n-split warps; weights read from global (L1-hot).
// ---------------------------------------------------------------------------

#define KB 2
typedef unsigned int u32;

__device__ __align__(16) u32 g_W0u[KB * 8192];          // l0 W  B-frag tf32
__device__ __align__(16) u32 g_Wlu[KB * 7 * 4096];      // l1..7 W B-frag tf32
__device__ __align__(16) float g_b [KB * 8 * 64];       // biases [k][l][n]
__device__ __align__(16) float g_h [KB * 8 * 64];       // hidden h [k][l][64]

__device__ __forceinline__ u32 tf32c(float f)
{ u32 u; asm("cvt.rna.tf32.f32 %0, %1;" : "=r"(u) : "f"(f)); return u; }

// ---------------------------------------------------------------------------
// Kernel 1a: h + bias. grid = 16 blocks (one per (k,l)), 256 threads.
// All matvecs 4-way split across the 256 threads; loads fully unrolled.
// ---------------------------------------------------------------------------
__global__ void __launch_bounds__(256) h_kernel(
    const float* __restrict__ latent_tokens,
    const float* __restrict__ token_embeddings,
    const float* __restrict__ h_W0,  const float* __restrict__ h_b0,
    const float* __restrict__ h_ln_s0, const float* __restrict__ h_ln_b0,
    const float* __restrict__ bb_W0, const float* __restrict__ bb_b0,
    const float* __restrict__ h_W,   const float* __restrict__ h_b,
    const float* __restrict__ h_ln_s, const float* __restrict__ h_ln_b,
    const float* __restrict__ bb_W,  const float* __restrict__ bb_b)
{
    __shared__ float chunk[128];
    __shared__ float part[4][64];
    __shared__ float pre[64];
    __shared__ float hbuf[64];
    __shared__ float bpart[4][64];

    const int tid = threadIdx.x;
    const int k   = blockIdx.x >> 3;
    const int l   = blockIdx.x & 7;
    const int q   = tid >> 6;       // group 0..3
    const int j   = tid & 63;       // output 0..63

    if (tid < 128)
        chunk[tid] = (tid < 64) ? __ldg(latent_tokens + (k * 8 + l) * 64 + tid)
                                : __ldg(token_embeddings + l * 64 + (tid - 64));
    __syncthreads();

    // h_pre = chunk @ hW + hb   (4-way split over the 128 inputs)
    const float* hWp = (l == 0) ? h_W0 : (h_W + (l - 1) * 128 * 64);
    {
        float acc = 0.f;
        #pragma unroll
        for (int i = 0; i < 32; i++) {
            int ii = q * 32 + i;
            acc = fmaf(chunk[ii], __ldg(hWp + ii * 64 + j), acc);
        }
        part[q][j] = acc;
    }
    __syncthreads();
    if (tid < 64) {
        float hb = (l == 0) ? __ldg(h_b0 + tid) : __ldg(h_b + (l - 1) * 64 + tid);
        pre[tid] = part[0][tid] + part[1][tid] + part[2][tid] + part[3][tid] + hb;
    }
    __syncthreads();
    if (tid < 64) {
        float s1 = 0.f, s2 = 0.f;
        #pragma unroll
        for (int i = 0; i < 64; i++) { float v = pre[i]; s1 += v; s2 += v * v; }
        float mu   = s1 * (1.f / 64.f);
        float var  = s2 * (1.f / 64.f) - mu * mu;
        float rstd = rsqrtf(var + 1e-6f);
        float ls = (l == 0) ? __ldg(h_ln_s0 + tid) : __ldg(h_ln_s + (l - 1) * 64 + tid);
        float lb = (l == 0) ? __ldg(h_ln_b0 + tid) : __ldg(h_ln_b + (l - 1) * 64 + tid);
        float h  = fmaxf(fmaf((pre[tid] - mu) * rstd, ls, lb), 0.f);
        hbuf[tid] = h;
        g_h[(k * 8 + l) * 64 + tid] = h;
    }
    __syncthreads();

    // bias = h @ bbW + bb  (4-way split over the 64-deep reduction)
    {
        const float* bWp = (l == 0) ? bb_W0 : (bb_W + (l - 1) * 64 * 64);
        float acc = 0.f;
        #pragma unroll
        for (int i = 0; i < 16; i++) {
            int jj = q * 16 + i;
            acc = fmaf(hbuf[jj], __ldg(bWp + jj * 64 + j), acc);
        }
        bpart[q][j] = acc;
    }
    __syncthreads();
    if (tid < 64) {
        float bb0 = (l == 0) ? __ldg(bb_b0 + tid) : __ldg(bb_b + (l - 1) * 64 + tid);
        g_b[(k * 8 + l) * 64 + tid] =
            bpart[0][tid] + bpart[1][tid] + bpart[2][tid] + bpart[3][tid] + bb0;
    }
}

// ---------------------------------------------------------------------------
// Kernel 1b: W streaming. grid = 16 x 32 splits = 512 blocks, 256 threads.
// Each thread computes one output o (64-deep fully unrolled j loop).
// ---------------------------------------------------------------------------
__global__ void __launch_bounds__(256) w_kernel(
    const float* __restrict__ w_W0, const float* __restrict__ w_b0,
    const float* __restrict__ w_W,  const float* __restrict__ w_b)
{
    __shared__ float hbuf[64];

    const int tid = threadIdx.x;
    const int bx  = blockIdx.x;
    const int sp  = bx & 31;
    const int kl  = bx >> 5;
    const int k   = kl >> 3;
    const int l   = kl & 7;

    if (tid < 64) hbuf[tid] = g_h[kl * 64 + tid];
    __syncthreads();

    const int OUT = (l == 0) ? 8064 : 4096;
    const int CH  = (OUT + 31) >> 5;               // 252 or 128
    const int o   = sp * CH + tid;
    const float* wWp = (l == 0) ? w_W0 : (w_W + (l - 1) * 64 * 4096);
    const float* wbp = (l == 0) ? w_b0 : (w_b + (l - 1) * 4096);

    if (tid < CH && o < OUT) {
        float acc = __ldg(wbp + o);
        #pragma unroll
        for (int j = 0; j < 64; j++)
            acc = fmaf(hbuf[j], __ldg(wWp + j * OUT + o), acc);
        int n, m;
        if (l == 0) { n = o / 126; m = o - n * 126; }
        else        { n = o >> 6;  m = o & 63; }
        int kt = m >> 3, kk = m & 7;
        int nt = n >> 3, nn = n & 7;
        int lane = nn * 4 + (kk & 3);
        int slot = kk >> 2;
        int idx  = (kt * 8 + nt) * 64 + lane * 2 + slot;
        if (l == 0) g_W0u[k * 8192 + idx] = tf32c(acc);
        else        g_Wlu[k * 28672 + (l - 1) * 4096 + idx] = tf32c(acc);
    }

    // zero-pad W0 rows m = 126,127 (once per k)
    if (l == 0 && sp == 0 && tid < 128) {
        int n = tid & 63, m = 126 + (tid >> 6);
        int kt = m >> 3, kk = m & 7;
        int nt = n >> 3, nn = n & 7;
        int idx = (kt * 8 + nt) * 64 + (nn * 4 + (kk & 3)) * 2 + (kk >> 2);
        g_W0u[k * 8192 + idx] = 0u;
    }
}

// ---------------------------------------------------------------------------
// Float-only accurate sin: 2-term Cody-Waite reduction by pi, then sinf.
// ---------------------------------------------------------------------------
__device__ __forceinline__ float acc_sin(float x)
{
    float q = rintf(x * 0.318309886183790672f);
    float r = fmaf(-q, 3.14159274101257324f, x);
    r = fmaf(-q, -8.74227800037e-8f, r);
    float s = sinf(r);
    return (((int)q) & 1) ? -s : s;
}

#define MMA_TF32(C, AV, BV) \
    asm volatile("mma.sync.aligned.m16n8k8.row.col.f32.tf32.tf32.f32 " \
        "{%0,%1,%2,%3}, {%4,%5,%6,%7}, {%8,%9}, {%0,%1,%2,%3};" \
        : "+f"((C)[0]), "+f"((C)[1]), "+f"((C)[2]), "+f"((C)[3]) \
        : "r"((AV).x), "r"((AV).y), "r"((AV).z), "r"((AV).w), \
          "r"((BV).x), "r"((BV).y))

// ---------------------------------------------------------------------------
// Kernel 2: tensor-core decoder. 512 blocks x 128 threads, 16 pts/block
// (k = bx >> 8). 4 warps = 4 n-splits of the single 16-point A-tile.
// Weights from GLOBAL (L1-hot). LN via smem partial exchange + syncthreads.
// ---------------------------------------------------------------------------
__global__ void __launch_bounds__(128, 6) decode_kernel(
    const float* __restrict__ rays,
    const float* __restrict__ ln_s0, const float* __restrict__ ln_b0,
    const float* __restrict__ ln_s,  const float* __restrict__ ln_b,
    const float* __restrict__ rgb_W, const float* __restrict__ rgb_b,
    float* __restrict__ out)
{
    __shared__ __align__(16) u32 sA[2048];
    __shared__ float  sBias[512];
    __shared__ float  sLN[1024];
    __shared__ float4 sRed[64];                   // 16 pts x 4 ns
    __shared__ float4 sRGB[64];

    const int tid  = threadIdx.x;
    const int ns   = tid >> 5;      // n-split 0..3
    const int lane = tid & 31;
    const int gid  = lane >> 2;     // row group 0..7
    const int tig  = lane & 3;      // thread in group
    const int bx   = blockIdx.x;
    const int k    = bx >> 8;

    const u32* W0g = g_W0u + k * 8192;
    const u32* Wlg = g_Wlu + k * 28672;

    // ---- stage biases + LN params ----
    #pragma unroll
    for (int i = tid; i < 512; i += 128) sBias[i] = __ldg(g_b + k * 512 + i);
    #pragma unroll
    for (int i = tid; i < 1024; i += 128) {
        int l = i >> 7, j = i & 127;
        float v;
        if (l == 0) v = (j < 64) ? __ldg(ln_s0 + j) : __ldg(ln_b0 + j - 64);
        else        v = (j < 64) ? __ldg(ln_s + (l - 1) * 64 + j)
                                 : __ldg(ln_b + (l - 1) * 64 + j - 64);
        sLN[i] = v;
    }

    // ---- positional encoding into A-fragment layout (8 lanes/point) ----
    {
        const int pb = tid >> 3;            // point in block 0..15
        const int s  = tid & 7;
        const float* r = rays + (bx * 16 + pb) * 6;
        float ox = __ldg(r + 0), oy = __ldg(r + 1), oz = __ldg(r + 2);
        float dx = __ldg(r + 3), dy = __ldg(r + 4), dz = __ldg(r + 5);
        float pv[6];
        pv[0] = dx; pv[1] = dy; pv[2] = dz;
        pv[3] = oy * dz - oz * dy;
        pv[4] = oz * dx - ox * dz;
        pv[5] = ox * dy - oy * dx;
        auto sta = [&](int m, float v) {
            int kt = m >> 3, c = m & 7;
            int ln = (pb & 7) * 4 + (c & 3);
            int sl = (pb >> 3) + 2 * (c >> 2);
            sA[kt * 128 + ln * 4 + sl] = tf32c(v);
        };
        if (s == 6) {
            #pragma unroll
            for (int cm = 0; cm < 6; cm++) sta(cm, pv[cm]);
        }
        if (s == 7) { sta(126, 0.f); sta(127, 0.f); }
        const float PIH = 1.57079632679489662f;
        for (int f = s; f < 10; f += 8) {
            float fr = (float)(1 << f);
            #pragma unroll
            for (int cm = 0; cm < 6; cm++) {
                float a = pv[cm] * fr;
                sta(6 + f * 6 + cm, acc_sin(a));
                sta(66 + f * 6 + cm, acc_sin(a + PIH));
            }
        }
    }
    __syncthreads();

    const int nt0 = 2 * ns;               // this warp's n-tiles
    const int pb0 = gid;                  // this thread's points: pb0, pb0+8

    float C[2][4];
    float y[2][4];

    #pragma unroll 1
    for (int l = 0; l < 8; l++) {
        const u32* Wl = (l == 0) ? W0g : (Wlg + (l - 1) * 4096);
        const int KT = (l == 0) ? 16 : 8;

        #pragma unroll
        for (int q = 0; q < 2; q++) {
            int n0 = (nt0 + q) * 8 + 2 * tig;
            float b0v = sBias[l * 64 + n0];
            float b1v = sBias[l * 64 + n0 + 1];
            C[q][0] = b0v; C[q][1] = b1v;
            C[q][2] = b0v; C[q][3] = b1v;
        }

        #pragma unroll 8
        for (int kt = 0; kt < KT; kt++) {
            uint4 av = *(const uint4*)(sA + kt * 128 + lane * 4);
            uint2 bv0 = __ldg((const uint2*)(Wl + (kt * 8 + nt0)     * 64 + lane * 2));
            uint2 bv1 = __ldg((const uint2*)(Wl + (kt * 8 + nt0 + 1) * 64 + lane * 2));
            MMA_TF32(C[0], av, bv0);
            MMA_TF32(C[1], av, bv1);
        }

        // ---- LN partials: shuffle in 4-lane group, combine via smem ----
        float s1a = 0.f, s2a = 0.f, s1b = 0.f, s2b = 0.f;
        #pragma unroll
        for (int q = 0; q < 2; q++) {
            s1a += C[q][0] + C[q][1];
            s2a  = fmaf(C[q][0], C[q][0], fmaf(C[q][1], C[q][1], s2a));
            s1b += C[q][2] + C[q][3];
            s2b  = fmaf(C[q][2], C[q][2], fmaf(C[q][3], C[q][3], s2b));
        }
        #pragma unroll
        for (int mm = 1; mm < 4; mm <<= 1) {
            s1a += __shfl_xor_sync(0xffffffffu, s1a, mm, 32);
            s2a += __shfl_xor_sync(0xffffffffu, s2a, mm, 32);
            s1b += __shfl_xor_sync(0xffffffffu, s1b, mm, 32);
            s2b += __shfl_xor_sync(0xffffffffu, s2b, mm, 32);
        }
        if (tig == 0)
            sRed[pb0 * 4 + ns] = make_float4(s1a, s2a, s1b, s2b);
        __syncthreads();

        float S1a = 0.f, S2a = 0.f, S1b = 0.f, S2b = 0.f;
        #pragma unroll
        for (int j = 0; j < 4; j++) {
            float4 v = sRed[pb0 * 4 + j];
            S1a += v.x; S2a += v.y; S1b += v.z; S2b += v.w;
        }
        float mu0 = S1a * (1.f / 64.f);
        float mu1 = S1b * (1.f / 64.f);
        float rs0 = rsqrtf(S2a * (1.f / 64.f) - mu0 * mu0 + 1e-6f);
        float rs1 = rsqrtf(S2b * (1.f / 64.f) - mu1 * mu1 + 1e-6f);

        #pragma unroll
        for (int q = 0; q < 2; q++) {
            int n0 = (nt0 + q) * 8 + 2 * tig;
            float ls0 = sLN[l * 128 + n0],      ls1 = sLN[l * 128 + n0 + 1];
            float lb0 = sLN[l * 128 + 64 + n0], lb1 = sLN[l * 128 + 64 + n0 + 1];
            y[q][0] = fmaxf(fmaf((C[q][0] - mu0) * rs0, ls0, lb0), 0.f);
            y[q][1] = fmaxf(fmaf((C[q][1] - mu0) * rs0, ls1, lb1), 0.f);
            y[q][2] = fmaxf(fmaf((C[q][2] - mu1) * rs1, ls0, lb0), 0.f);
            y[q][3] = fmaxf(fmaf((C[q][3] - mu1) * rs1, ls1, lb1), 0.f);
            if (l < 7) {
                int nt = nt0 + q;
                int c0 = n0 & 7;
                int b0i = nt * 128 + (gid * 4 + (c0 & 3)) * 4 + 2 * (c0 >> 2);
                sA[b0i]     = tf32c(y[q][0]);     // row gid
                sA[b0i + 1] = tf32c(y[q][2]);     // row gid+8
                int c1 = c0 + 1;
                int b1i = nt * 128 + (gid * 4 + (c1 & 3)) * 4 + 2 * (c1 >> 2);
                sA[b1i]     = tf32c(y[q][1]);
                sA[b1i + 1] = tf32c(y[q][3]);
            }
        }
        if (l < 7) __syncthreads();
    }

    // ---- rgb head + sigmoid ----
    {
        float r0[3] = {0.f, 0.f, 0.f};
        float r1[3] = {0.f, 0.f, 0.f};
        #pragma unroll
        for (int q = 0; q < 2; q++) {
            int n0 = (nt0 + q) * 8 + 2 * tig;
            #pragma unroll
            for (int ch = 0; ch < 3; ch++) {
                float w0 = __ldg(rgb_W + n0 * 3 + ch);
                float w1 = __ldg(rgb_W + (n0 + 1) * 3 + ch);
                r0[ch] = fmaf(y[q][0], w0, fmaf(y[q][1], w1, r0[ch]));
                r1[ch] = fmaf(y[q][2], w0, fmaf(y[q][3], w1, r1[ch]));
            }
        }
        #pragma unroll
        for (int mm = 1; mm < 4; mm <<= 1) {
            #pragma unroll
            for (int ch = 0; ch < 3; ch++) {
                r0[ch] += __shfl_xor_sync(0xffffffffu, r0[ch], mm, 32);
                r1[ch] += __shfl_xor_sync(0xffffffffu, r1[ch], mm, 32);
            }
        }
        if (tig == 0) {
            sRGB[pb0 * 4 + ns]       = make_float4(r0[0], r0[1], r0[2], 0.f);
            sRGB[(pb0 + 8) * 4 + ns] = make_float4(r1[0], r1[1], r1[2], 0.f);
        }
        __syncthreads();
        if (tid < 16) {
            float4 a0 = sRGB[tid * 4 + 0];
            float4 a1 = sRGB[tid * 4 + 1];
            float4 a2 = sRGB[tid * 4 + 2];
            float4 a3 = sRGB[tid * 4 + 3];
            float v0 = a0.x + a1.x + a2.x + a3.x + __ldg(rgb_b + 0);
            float v1 = a0.y + a1.y + a2.y + a3.y + __ldg(rgb_b + 1);
            float v2 = a0.z + a1.z + a2.z + a3.z + __ldg(rgb_b + 2);
            int gp = bx * 16 + tid;
            out[gp * 3 + 0] = 1.f / (1.f + expf(-v0));
            out[gp * 3 + 1] = 1.f / (1.f + expf(-v1));
            out[gp * 3 + 2] = 1.f / (1.f + expf(-v2));
        }
    }
}

// ---------------------------------------------------------------------------
extern "C" void kernel_launch(void* const* d_in, const int* in_sizes, int n_in,
                              void* d_out, int out_size)
{
    const float* rays    = (const float*)d_in[0];
    const float* lat     = (const float*)d_in[1];
    const float* temb    = (const float*)d_in[2];
    const float* h_W0    = (const float*)d_in[3];
    const float* h_b0    = (const float*)d_in[4];
    const float* h_ln_s0 = (const float*)d_in[5];
    const float* h_ln_b0 = (const float*)d_in[6];
    const float* w_W0    = (const float*)d_in[7];
    const float* w_b0    = (const float*)d_in[8];
    const float* bb_W0   = (const float*)d_in[9];
    const float* bb_b0   = (const float*)d_in[10];
    const float* ln_s0   = (const float*)d_in[11];
    const float* ln_b0   = (const float*)d_in[12];
    const float* h_W     = (const float*)d_in[13];
    const float* h_b     = (const float*)d_in[14];
    const float* h_ln_s  = (const float*)d_in[15];
    const float* h_ln_b  = (const float*)d_in[16];
    const float* w_W     = (const float*)d_in[17];
    const float* w_b     = (const float*)d_in[18];
    const float* bb_W    = (const float*)d_in[19];
    const float* bb_b    = (const float*)d_in[20];
    const float* ln_s    = (const float*)d_in[21];
    const float* ln_b    = (const float*)d_in[22];
    const float* rgb_W   = (const float*)d_in[23];
    const float* rgb_b   = (const float*)d_in[24];
    float* out = (float*)d_out;

    h_kernel<<<16, 256>>>(lat, temb, h_W0, h_b0, h_ln_s0, h_ln_b0,
                          bb_W0, bb_b0, h_W, h_b, h_ln_s, h_ln_b,
                          bb_W, bb_b);
    w_kernel<<<512, 256>>>(w_W0, w_b0, w_W, w_b);
    decode_kernel<<<512, 128>>>(rays, ln_s0, ln_b0, ln_s, ln_b,
                                rgb_W, rgb_b, out);
}